// round 6
// baseline (speedup 1.0000x reference)
#include <cuda_runtime.h>

// RasterizePointsXYsBlending — scatter + shared-weight composite.
// B=2, P=2048, C=64, SIZE=128, K=8, RADIUS=1.5px, RAD_POW=2, TAU=1.
//
//  K1 (fused, 320 blocks x 256 thr):
//     blocks [0,256):  transpose src [B,C,P] -> srcT [B,P,C] (smem tile)
//     blocks [256,320): scatter — thread per (point, bbox-row): exact
//                       inside-test on <=4 pixels, atomic append
//                       (z, d2, idx) to the pixel's 16-slot list.
//  K2 (composite, 1024 blocks x (32,8)):
//     Phase A: warp 0 = one thread per pixel: top-8 by z, compositing
//              weights, compacted (w, idx) pairs -> SoA smem + count.
//              Resets the pixel counter (d_cnt zero-init invariant).
//     Phase B: 8 warps x 8 channels/thread: loop over the ~0.85 avg
//              selected points, float4 gathers from srcT, coalesced stores.

#define BN 2
#define PN 2048
#define CN 64
#define SZ 128
#define KN 8
#define BIGF 1e10f
// r_ndc = 1.5/128*2 = 3*2^-7 ; r2 = 9*2^-14 (exact fp32)
#define R2 0.00054931640625f

#define CAPP 16                       // per-pixel list capacity (mean ~0.9)
#define NPIX (BN * SZ * SZ)           // 32768
#define TRB 256                       // transpose blocks
#define SCB 64                        // scatter blocks (64*256 = BN*PN*4)

__device__ float  d_srcT[BN * PN * CN];   // src transposed to [b,p,c]
__device__ int    d_cnt[NPIX];            // per-pixel counts (invariant: 0)
__device__ float4 d_list[NPIX * CAPP];    // (z, d2, bitcast idx, -)

// ---------------------------------------------------------------- kernel 1
__global__ __launch_bounds__(256)
void prep_kernel(const float* __restrict__ src, const float* __restrict__ pts)
{
    if (blockIdx.x < TRB) {
        // ---------------- transpose half: 32x32 smem tile ----------------
        __shared__ float t[32][33];

        const int x  = threadIdx.x & 31;
        const int y  = threadIdx.x >> 5;             // 0..7
        const int p0 = (blockIdx.x & 63) * 32;       // 64 p-tiles
        const int c0 = ((blockIdx.x >> 6) & 1) * 32; // 2 c-tiles
        const int b  = blockIdx.x >> 7;              // 2 batches

        const float* sb = src + ((size_t)b * CN << 11);
#pragma unroll
        for (int j = 0; j < 4; ++j)
            t[y + 8 * j][x] = sb[((size_t)(c0 + y + 8 * j) << 11) + p0 + x];
        __syncthreads();

        float* db = d_srcT + (((size_t)b * PN) << 6);
#pragma unroll
        for (int j = 0; j < 4; ++j)
            db[((size_t)(p0 + y + 8 * j) << 6) + c0 + x] = t[x][y + 8 * j];
    } else {
        // ---------------- scatter half: (point, bbox-row) ----------------
        const int g  = (blockIdx.x - TRB) * 256 + threadIdx.x;
        const int ry = g & 3;
        const int gp = g >> 2;                 // global point id
        const int b  = gp >> 11;
        const int p  = gp & (PN - 1);

        const float px = -pts[gp * 3 + 0];     // sign flip from the forward
        const float py = -pts[gp * 3 + 1];
        const float pz =  pts[gp * 3 + 2];

        // pixel coords of the point: ndc(i) = 1-(2i+1)/128
        const float u = (1.0f - px) * 64.0f - 0.5f;   // w
        const float v = (1.0f - py) * 64.0f - 0.5f;   // h

        // radius 1.5 px + fp margin
        const int wlo = max(0,      (int)ceilf (u - 1.6f));
        const int whi = min(SZ - 1, (int)floorf(u + 1.6f));
        const int hlo = max(0,      (int)ceilf (v - 1.6f));
        const int hhi = min(SZ - 1, (int)floorf(v + 1.6f));

        const int h = hlo + ry;
        if (h > hhi || wlo > whi) return;

        const float ndcy = 1.0f - (2.0f * (float)h + 1.0f) / 128.0f;
        const float dy   = ndcy - py;
        const float dy2  = __fmul_rn(dy, dy);

        for (int w = wlo; w <= whi; ++w) {
            const float ndcx = 1.0f - (2.0f * (float)w + 1.0f) / 128.0f;
            const float dx   = ndcx - px;
            // mul/mul/add, non-fused: matches reference rounding exactly
            const float d2 = __fadd_rn(__fmul_rn(dx, dx), dy2);
            if (d2 <= R2) {
                const int pix  = ((b * SZ) + h) * SZ + w;
                const int slot = atomicAdd(&d_cnt[pix], 1);
                if (slot < CAPP)
                    d_list[pix * CAPP + slot] =
                        make_float4(pz, d2, __int_as_float(p), 0.0f);
            }
        }
    }
}

// ---------------------------------------------------------------- kernel 2
// Block (32,8): 32 pixels x 8 channel-groups (8 channels per thread).
// grid = BN*SZ*(SZ/32) = 1024 blocks.
__global__ __launch_bounds__(256)
void composite_kernel(float* __restrict__ out)
{
    __shared__ float s_w[KN][32];   // compacted weights per pixel
    __shared__ int   s_i[KN][32];   // compacted point indices per pixel
    __shared__ int   s_n[32];       // number of compacted entries

    const int wt = blockIdx.x & 3;
    const int h  = (blockIdx.x >> 2) & (SZ - 1);
    const int b  = blockIdx.x >> 9;
    const int x  = threadIdx.x;              // pixel lane
    const int w  = wt * 32 + x;
    const int pix = ((b * SZ) + h) * SZ + w;

    // -------- Phase A: warp 0 computes selection + weights per pixel -----
    if (threadIdx.y == 0) {
        const int cnt = min(d_cnt[pix], CAPP);
        d_cnt[pix] = 0;                      // restore all-zero invariant

        float zb[KN], db[KN];
        int   ib[KN];
#pragma unroll
        for (int k = 0; k < KN; ++k) { zb[k] = BIGF; db[k] = 0.0f; ib[k] = 0; }

        const float4* lp = d_list + pix * CAPP;
        for (int i = 0; i < cnt; ++i) {
            float4 e = lp[i];
            if (e.x < zb[KN - 1]) {
                float cz = e.x, cd = e.y;
                int   ci = __float_as_int(e.z);
                bool  ins = false;
#pragma unroll
                for (int k = 0; k < KN; ++k) {
                    bool sw = ins | (cz < zb[k]);
                    if (sw) {
                        float tz = zb[k]; zb[k] = cz; cz = tz;
                        float td = db[k]; db[k] = cd; cd = td;
                        int   ti = ib[k]; ib[k] = ci; ci = ti;
                        ins = true;
                    }
                }
            }
        }

        // weights w_k = a_k * prod_{j<k}(1 - a_j); compact nonzero terms
        int ns = 0;
        float T = 1.0f;
#pragma unroll
        for (int k = 0; k < KN; ++k) {
            if (zb[k] < BIGF) {
                float dist = __fdiv_rn(db[k], R2);
                dist = fminf(fmaxf(dist, 0.001f), 1.0f);
                float a = 1.0f - __fsqrt_rn(dist);
                float wk = a * T;
                T = T * (1.0f - a);
                if (wk > 0.0f) {
                    s_w[ns][x] = wk;
                    s_i[ns][x] = ib[k];
                    ++ns;
                }
            }
        }
        s_n[x] = ns;
    }
    __syncthreads();

    // -------- Phase B: all warps gather+accumulate 8 channels each -------
    const int   cg = threadIdx.y;            // channel group (8 channels)
    const int   ns = s_n[x];
    const float* sbase = d_srcT + (((size_t)b * PN) << 6) + cg * 8;

    float acc[8];
#pragma unroll
    for (int j = 0; j < 8; ++j) acc[j] = 0.0f;

    for (int i = 0; i < ns; ++i) {
        const float wk  = s_w[i][x];
        const int   idx = s_i[i][x];
        const float4* s4 = (const float4*)(sbase + ((size_t)idx << 6));
        float4 v0 = s4[0];
        float4 v1 = s4[1];
        acc[0] = fmaf(wk, v0.x, acc[0]);
        acc[1] = fmaf(wk, v0.y, acc[1]);
        acc[2] = fmaf(wk, v0.z, acc[2]);
        acc[3] = fmaf(wk, v0.w, acc[3]);
        acc[4] = fmaf(wk, v1.x, acc[4]);
        acc[5] = fmaf(wk, v1.y, acc[5]);
        acc[6] = fmaf(wk, v1.z, acc[6]);
        acc[7] = fmaf(wk, v1.w, acc[7]);
    }

    // out[b,c,h,w]; lane = w -> coalesced 128B stores
    float* ob = out + (((size_t)(b * CN + cg * 8)) * SZ + h) * SZ + w;
#pragma unroll
    for (int j = 0; j < 8; ++j)
        ob[(size_t)j * SZ * SZ] = acc[j];
}

// ---------------------------------------------------------------- launch
extern "C" void kernel_launch(void* const* d_in, const int* in_sizes, int n_in,
                              void* d_out, int out_size)
{
    const float* pts = (const float*)d_in[0];  // [B,P,3]
    const float* src = (const float*)d_in[1];  // [B,C,P]
    float* out = (float*)d_out;                // [B,C,H,W]

    prep_kernel<<<TRB + SCB, 256>>>(src, pts);
    composite_kernel<<<BN * SZ * (SZ / 32), dim3(32, 8)>>>(out);
}

// round 8
// speedup vs baseline: 1.1194x; 1.1194x over previous
#include <cuda_runtime.h>

// RasterizePointsXYsBlending — scatter-with-alpha + order-independent composite.
// B=2, P=2048, C=64, SIZE=128, K=8, RADIUS=1.5px, RAD_POW=2, TAU=1.
//
//  K1 (fused, 272 blocks x 1024 thr):
//     blocks [0,256):  transpose src [B,C,P] -> srcT [B,P,C]
//                      (32x32 smem tile, 1 element/thread)
//     blocks [256,272): scatter — thread per (point, bbox-row): exact
//                       inside-test on <=4 pixels, alpha via the reference's
//                       exact div/clamp/sqrt, atomic append (z, alpha, idx)
//                       to the pixel's 16-slot list.
//  K2 (composite, 1024 blocks x (32,4)): 4 threads/pixel, 16 channels each.
//     ALL threads read the pixel counter, then __syncthreads, then one
//     thread clears it (read-before-clear; fixes the R7 cross-warp race).
//     cnt<=8 fast path: order-independent weights w_i = a_i*prod_{z_j<z_i}
//     (1-a_j); cold top-8 insertion fallback for cnt>8.

#define BN 2
#define PN 2048
#define CN 64
#define SZ 128
#define KN 8
#define BIGF 1e10f
// r_ndc = 1.5/128*2 = 3*2^-7 ; r2 = 9*2^-14 (exact fp32)
#define R2 0.00054931640625f

#define CAPP 16                       // per-pixel list capacity (mean ~0.9)
#define NPIX (BN * SZ * SZ)           // 32768
#define TRB 256                       // transpose blocks
#define SCB 16                        // scatter blocks (16*1024 = BN*PN*4)

__device__ float  d_srcT[BN * PN * CN];   // src transposed to [b,p,c]
__device__ int    d_cnt[NPIX];            // per-pixel counts (invariant: 0)
__device__ float4 d_list[NPIX * CAPP];    // (z, alpha, bitcast idx, -)

// ---------------------------------------------------------------- kernel 1
__global__ __launch_bounds__(1024)
void prep_kernel(const float* __restrict__ src, const float* __restrict__ pts)
{
    if (blockIdx.x < TRB) {
        // ------------- transpose: 32x32 tile, 1 element/thread -----------
        __shared__ float t[32][33];

        const int x  = threadIdx.x & 31;
        const int y  = threadIdx.x >> 5;             // 0..31
        const int p0 = (blockIdx.x & 63) * 32;       // 64 p-tiles
        const int c0 = ((blockIdx.x >> 6) & 1) * 32; // 2 c-tiles
        const int b  = blockIdx.x >> 7;              // 2 batches

        t[y][x] = src[((size_t)(b * CN + c0 + y) << 11) + p0 + x];
        __syncthreads();
        d_srcT[(((size_t)(b * PN + p0 + y)) << 6) + c0 + x] = t[x][y];
    } else {
        // ---------------- scatter: (point, bbox-row) ---------------------
        const int g  = (blockIdx.x - TRB) * 1024 + threadIdx.x;
        const int ry = g & 3;
        const int gp = g >> 2;                 // global point id
        const int b  = gp >> 11;
        const int p  = gp & (PN - 1);

        const float px = -pts[gp * 3 + 0];     // sign flip from the forward
        const float py = -pts[gp * 3 + 1];
        const float pz =  pts[gp * 3 + 2];

        // pixel coords of the point: ndc(i) = 1-(2i+1)/128
        const float u = (1.0f - px) * 64.0f - 0.5f;   // w
        const float v = (1.0f - py) * 64.0f - 0.5f;   // h

        // radius 1.5 px + fp margin
        const int wlo = max(0,      (int)ceilf (u - 1.6f));
        const int whi = min(SZ - 1, (int)floorf(u + 1.6f));
        const int hlo = max(0,      (int)ceilf (v - 1.6f));
        const int hhi = min(SZ - 1, (int)floorf(v + 1.6f));

        const int h = hlo + ry;
        if (h > hhi || wlo > whi) return;

        const float ndcy = 1.0f - (2.0f * (float)h + 1.0f) / 128.0f;
        const float dy   = ndcy - py;
        const float dy2  = __fmul_rn(dy, dy);

        for (int w = wlo; w <= whi; ++w) {
            const float ndcx = 1.0f - (2.0f * (float)w + 1.0f) / 128.0f;
            const float dx   = ndcx - px;
            // mul/mul/add, non-fused: matches reference rounding exactly
            const float d2 = __fadd_rn(__fmul_rn(dx, dx), dy2);
            if (d2 <= R2) {
                // alpha with the reference's exact op sequence
                float dist = __fdiv_rn(d2, R2);
                dist = fminf(fmaxf(dist, 0.001f), 1.0f);
                const float a = 1.0f - __fsqrt_rn(dist);

                const int pix  = ((b * SZ) + h) * SZ + w;
                const int slot = atomicAdd(&d_cnt[pix], 1);
                if (slot < CAPP)
                    d_list[pix * CAPP + slot] =
                        make_float4(pz, a, __int_as_float(p), 0.0f);
            }
        }
    }
}

// ---------------------------------------------------------------- kernel 2
// Block (32,4): 32 pixels x 4 channel-groups (16 channels per thread).
// grid = BN*SZ*(SZ/32) = 1024 blocks.
__global__ __launch_bounds__(128)
void composite_kernel(float* __restrict__ out)
{
    const int wt = blockIdx.x & 3;
    const int h  = (blockIdx.x >> 2) & (SZ - 1);
    const int b  = blockIdx.x >> 9;
    const int x  = threadIdx.x;
    const int w  = wt * 32 + x;
    const int cg = threadIdx.y;              // channel group: 16 channels
    const int pix = ((b * SZ) + h) * SZ + w;

    // read-before-clear: every warp loads the counter, barrier, then clear.
    const int cnt = min(d_cnt[pix], CAPP);
    __syncthreads();
    if (cg == 0) d_cnt[pix] = 0;             // restore all-zero invariant

    float acc[16];
#pragma unroll
    for (int j = 0; j < 16; ++j) acc[j] = 0.0f;

    const float4* lp = d_list + pix * CAPP;
    const float*  sbase = d_srcT + (((size_t)b * PN) << 6) + cg * 16;

    if (cnt <= KN) {
        // ---- common path: all points selected; order-independent weights
        for (int i = 0; i < cnt; ++i) {
            const float4 ei = lp[i];
            float wi = ei.y;                              // a_i
            for (int j = 0; j < cnt; ++j) {
                if (j == i) continue;
                const float4 ej = lp[j];
                if (ej.x < ei.x) wi *= (1.0f - ej.y);
            }
            if (wi > 0.0f) {
                const float4* s4 = (const float4*)
                    (sbase + ((size_t)__float_as_int(ei.z) << 6));
#pragma unroll
                for (int q = 0; q < 4; ++q) {
                    const float4 v = s4[q];
                    acc[4 * q + 0] = fmaf(wi, v.x, acc[4 * q + 0]);
                    acc[4 * q + 1] = fmaf(wi, v.y, acc[4 * q + 1]);
                    acc[4 * q + 2] = fmaf(wi, v.z, acc[4 * q + 2]);
                    acc[4 * q + 3] = fmaf(wi, v.w, acc[4 * q + 3]);
                }
            }
        }
    } else {
        // ---- cold path: top-8 by z (insertion), then sequential cumprod
        float zb[KN], ab[KN];
        int   ib[KN];
#pragma unroll
        for (int k = 0; k < KN; ++k) { zb[k] = BIGF; ab[k] = 0.0f; ib[k] = 0; }
        for (int i = 0; i < cnt; ++i) {
            const float4 e = lp[i];
            if (e.x < zb[KN - 1]) {
                float cz = e.x, ca = e.y;
                int   ci = __float_as_int(e.z);
                bool  ins = false;
#pragma unroll
                for (int k = 0; k < KN; ++k) {
                    bool sw = ins | (cz < zb[k]);
                    if (sw) {
                        float tz = zb[k]; zb[k] = cz; cz = tz;
                        float ta = ab[k]; ab[k] = ca; ca = ta;
                        int   ti = ib[k]; ib[k] = ci; ci = ti;
                        ins = true;
                    }
                }
            }
        }
        float T = 1.0f;
#pragma unroll
        for (int k = 0; k < KN; ++k) {
            if (zb[k] < BIGF) {
                const float wi = ab[k] * T;
                T = T * (1.0f - ab[k]);
                if (wi > 0.0f) {
                    const float4* s4 = (const float4*)
                        (sbase + ((size_t)ib[k] << 6));
#pragma unroll
                    for (int q = 0; q < 4; ++q) {
                        const float4 v = s4[q];
                        acc[4 * q + 0] = fmaf(wi, v.x, acc[4 * q + 0]);
                        acc[4 * q + 1] = fmaf(wi, v.y, acc[4 * q + 1]);
                        acc[4 * q + 2] = fmaf(wi, v.z, acc[4 * q + 2]);
                        acc[4 * q + 3] = fmaf(wi, v.w, acc[4 * q + 3]);
                    }
                }
            }
        }
    }

    // out[b,c,h,w]; lane = w -> coalesced 128B stores
    float* ob = out + (((size_t)(b * CN + cg * 16)) * SZ + h) * SZ + w;
#pragma unroll
    for (int j = 0; j < 16; ++j)
        ob[(size_t)j * SZ * SZ] = acc[j];
}

// ---------------------------------------------------------------- launch
extern "C" void kernel_launch(void* const* d_in, const int* in_sizes, int n_in,
                              void* d_out, int out_size)
{
    const float* pts = (const float*)d_in[0];  // [B,P,3]
    const float* src = (const float*)d_in[1];  // [B,C,P]
    float* out = (float*)d_out;                // [B,C,H,W]

    prep_kernel<<<TRB + SCB, 1024>>>(src, pts);
    composite_kernel<<<BN * SZ * (SZ / 32), dim3(32, 4)>>>(out);
}

// round 9
// speedup vs baseline: 1.1385x; 1.0171x over previous
#include <cuda_runtime.h>

// RasterizePointsXYsBlending — single persistent kernel with grid barrier.
// B=2, P=2048, C=64, SIZE=128, K=8, RADIUS=1.5px, RAD_POW=2, TAU=1.
//
// Grid = 148 blocks x 1024 threads (<= SM count -> all co-resident, wave 1).
// Phase 1a: transpose src [B,C,P] -> srcT [B,P,C] (32x32 smem tiles,
//           tiles grid-strided over blocks).
// Phase 1b: blocks 108..147: scatter — thread per (point, bbox-row):
//           exact inside-test on <=4 pixels, alpha via the reference's exact
//           div/clamp/sqrt, atomic append (z, alpha, idx) to 16-slot lists.
// Grid barrier: two-counter self-resetting protocol (d_bin arrivals with
//           spin; d_bout exits; last exiting block resets both to 0 — the
//           all-zero invariant holds at every kernel boundary).
// Phase 2:  composite — 4 consecutive lanes per pixel (16 channels each);
//           pixel counter broadcast via __shfl_sync (leader loads, shfl
//           orders, leader clears: warp-local read-before-clear).
//           cnt<=8 fast path: order-independent weights
//           w_i = a_i * prod_{z_j<z_i}(1-a_j); top-8 insertion fallback.

#define BN 2
#define PN 2048
#define CN 64
#define SZ 128
#define KN 8
#define BIGF 1e10f
// r_ndc = 1.5/128*2 = 3*2^-7 ; r2 = 9*2^-14 (exact fp32)
#define R2 0.00054931640625f

#define CAPP 16                       // per-pixel list capacity (mean ~0.9)
#define NPIX (BN * SZ * SZ)           // 32768
#define NBLK 148
#define NTHR 1024
#define NTILE 256                     // 32x32 transpose tiles
#define SCAT_FIRST 108                // blocks [108,148) run the scatter
#define NSCAT (BN * PN * 4)           // 16384 scatter items

__device__ float  d_srcT[BN * PN * CN];   // src transposed to [b,p,c]
__device__ int    d_cnt[NPIX];            // per-pixel counts (invariant: 0)
__device__ float4 d_list[NPIX * CAPP];    // (z, alpha, bitcast idx, -)
__device__ int    d_bin;                  // barrier arrivals (invariant: 0)
__device__ int    d_bout;                 // barrier exits    (invariant: 0)

__global__ __launch_bounds__(NTHR, 1)
void fused_kernel(const float* __restrict__ pts,
                  const float* __restrict__ src,
                  float* __restrict__ out)
{
    __shared__ float tile[32][33];
    const int tid = threadIdx.x;
    const int bid = blockIdx.x;

    // ---------------- phase 1a: transpose (grid-strided tiles) -----------
    for (int t = bid; t < NTILE; t += NBLK) {
        const int b  = t >> 7;
        const int c0 = ((t >> 6) & 1) * 32;
        const int p0 = (t & 63) * 32;
        const int x  = tid & 31;
        const int y  = tid >> 5;
        tile[y][x] = src[((size_t)(b * CN + c0 + y) << 11) + p0 + x];
        __syncthreads();
        d_srcT[((size_t)(b * PN + p0 + y) << 6) + c0 + x] = tile[x][y];
        __syncthreads();
    }

    // ---------------- phase 1b: scatter (blocks 108..147) ----------------
    if (bid >= SCAT_FIRST) {
        const int s = (bid - SCAT_FIRST) * NTHR + tid;
        if (s < NSCAT) {
            const int ry = s & 3;
            const int gp = s >> 2;                 // global point id
            const int b  = gp >> 11;
            const int p  = gp & (PN - 1);

            const float px = -pts[gp * 3 + 0];     // sign flip from forward
            const float py = -pts[gp * 3 + 1];
            const float pz =  pts[gp * 3 + 2];

            // pixel coords: ndc(i) = 1-(2i+1)/128
            const float u = (1.0f - px) * 64.0f - 0.5f;   // w
            const float v = (1.0f - py) * 64.0f - 0.5f;   // h

            const int wlo = max(0,      (int)ceilf (u - 1.6f));
            const int whi = min(SZ - 1, (int)floorf(u + 1.6f));
            const int hlo = max(0,      (int)ceilf (v - 1.6f));
            const int hhi = min(SZ - 1, (int)floorf(v + 1.6f));

            const int h = hlo + ry;
            if (h <= hhi && wlo <= whi) {
                const float ndcy = 1.0f - (2.0f * (float)h + 1.0f) / 128.0f;
                const float dy   = ndcy - py;
                const float dy2  = __fmul_rn(dy, dy);

                for (int w = wlo; w <= whi; ++w) {
                    const float ndcx = 1.0f - (2.0f * (float)w + 1.0f) / 128.0f;
                    const float dx   = ndcx - px;
                    // non-fused: matches reference rounding at the boundary
                    const float d2 = __fadd_rn(__fmul_rn(dx, dx), dy2);
                    if (d2 <= R2) {
                        // alpha with the reference's exact op sequence
                        float dist = __fdiv_rn(d2, R2);
                        dist = fminf(fmaxf(dist, 0.001f), 1.0f);
                        const float a = 1.0f - __fsqrt_rn(dist);

                        const int pix  = ((b * SZ) + h) * SZ + w;
                        const int slot = atomicAdd(&d_cnt[pix], 1);
                        if (slot < CAPP)
                            d_list[pix * CAPP + slot] =
                                make_float4(pz, a, __int_as_float(p), 0.0f);
                    }
                }
            }
        }
    }

    // ---------------- grid barrier (self-resetting) -----------------------
    __syncthreads();
    if (tid == 0) {
        __threadfence();                       // publish phase-1 writes
        atomicAdd(&d_bin, 1);
        while (*(volatile int*)&d_bin < NBLK) __nanosleep(32);
        __threadfence();                       // acquire
    }
    __syncthreads();

    // ---------------- phase 2: composite ---------------------------------
    const int item = bid * NTHR + tid;         // [0, 151552)
    if (item < NPIX * 4) {
        const int pix  = item >> 2;            // 4 consecutive lanes / pixel
        const int cg   = item & 3;             // channel group: 16 channels
        const int lane = tid & 31;

        const int w = pix & (SZ - 1);
        const int h = (pix >> 7) & (SZ - 1);
        const int b = pix >> 14;

        // leader lane of the 4-group loads the counter, shfl broadcasts,
        // leader clears afterwards (shfl orders read before clear).
        int craw = 0;
        if ((lane & 3) == 0) craw = d_cnt[pix];
        int cnt = __shfl_sync(0xffffffffu, craw, lane & ~3);
        if ((lane & 3) == 0) d_cnt[pix] = 0;   // restore all-zero invariant
        cnt = min(cnt, CAPP);

        float acc[16];
#pragma unroll
        for (int j = 0; j < 16; ++j) acc[j] = 0.0f;

        const float4* lp = d_list + pix * CAPP;
        const float*  sbase = d_srcT + (((size_t)b * PN) << 6) + cg * 16;

        if (cnt <= KN) {
            // common path: all points selected; order-independent weights
            for (int i = 0; i < cnt; ++i) {
                const float4 ei = lp[i];
                float wi = ei.y;                          // a_i
                for (int j = 0; j < cnt; ++j) {
                    if (j == i) continue;
                    const float4 ej = lp[j];
                    if (ej.x < ei.x) wi *= (1.0f - ej.y);
                }
                if (wi > 0.0f) {
                    const float4* s4 = (const float4*)
                        (sbase + ((size_t)__float_as_int(ei.z) << 6));
#pragma unroll
                    for (int q = 0; q < 4; ++q) {
                        const float4 v = s4[q];
                        acc[4 * q + 0] = fmaf(wi, v.x, acc[4 * q + 0]);
                        acc[4 * q + 1] = fmaf(wi, v.y, acc[4 * q + 1]);
                        acc[4 * q + 2] = fmaf(wi, v.z, acc[4 * q + 2]);
                        acc[4 * q + 3] = fmaf(wi, v.w, acc[4 * q + 3]);
                    }
                }
            }
        } else {
            // cold path: top-8 by z (insertion), then sequential cumprod
            float zb[KN], ab[KN];
            int   ib[KN];
#pragma unroll
            for (int k = 0; k < KN; ++k) { zb[k] = BIGF; ab[k] = 0.0f; ib[k] = 0; }
            for (int i = 0; i < cnt; ++i) {
                const float4 e = lp[i];
                if (e.x < zb[KN - 1]) {
                    float cz = e.x, ca = e.y;
                    int   ci = __float_as_int(e.z);
                    bool  ins = false;
#pragma unroll
                    for (int k = 0; k < KN; ++k) {
                        bool sw = ins | (cz < zb[k]);
                        if (sw) {
                            float tz = zb[k]; zb[k] = cz; cz = tz;
                            float ta = ab[k]; ab[k] = ca; ca = ta;
                            int   ti = ib[k]; ib[k] = ci; ci = ti;
                            ins = true;
                        }
                    }
                }
            }
            float T = 1.0f;
#pragma unroll
            for (int k = 0; k < KN; ++k) {
                if (zb[k] < BIGF) {
                    const float wi = ab[k] * T;
                    T = T * (1.0f - ab[k]);
                    if (wi > 0.0f) {
                        const float4* s4 = (const float4*)
                            (sbase + ((size_t)ib[k] << 6));
#pragma unroll
                        for (int q = 0; q < 4; ++q) {
                            const float4 v = s4[q];
                            acc[4 * q + 0] = fmaf(wi, v.x, acc[4 * q + 0]);
                            acc[4 * q + 1] = fmaf(wi, v.y, acc[4 * q + 1]);
                            acc[4 * q + 2] = fmaf(wi, v.z, acc[4 * q + 2]);
                            acc[4 * q + 3] = fmaf(wi, v.w, acc[4 * q + 3]);
                        }
                    }
                }
            }
        }

        // out[b,c,h,w]
        float* ob = out + (((size_t)(b * CN + cg * 16)) * SZ + h) * SZ + w;
#pragma unroll
        for (int j = 0; j < 16; ++j)
            ob[(size_t)j * SZ * SZ] = acc[j];
    }

    // ---------------- barrier counter reset ------------------------------
    __syncthreads();
    if (tid == 0) {
        const int old = atomicAdd(&d_bout, 1);
        if (old == NBLK - 1) {          // last block out: restore invariant
            *(volatile int*)&d_bin  = 0;
            *(volatile int*)&d_bout = 0;
        }
    }
}

// ---------------------------------------------------------------- launch
extern "C" void kernel_launch(void* const* d_in, const int* in_sizes, int n_in,
                              void* d_out, int out_size)
{
    const float* pts = (const float*)d_in[0];  // [B,P,3]
    const float* src = (const float*)d_in[1];  // [B,C,P]
    float* out = (float*)d_out;                // [B,C,H,W]

    fused_kernel<<<NBLK, NTHR>>>(pts, src, out);
}